// round 1
// baseline (speedup 1.0000x reference)
#include <cuda_runtime.h>

// Problem constants
#define BB    16
#define NIN   1024
#define DIN   16
#define MM    512
#define NCHUNK 32                 // number of n-chunks
#define CHUNK (NIN / NCHUNK)      // 32 n per CTA
#define LN_EPS 1e-5f

// Deterministic per-chunk partial accumulators for nv: [chunk][b][m][16]
__device__ float g_partial[NCHUNK * BB * MM * 16];

// Main kernel: one CTA per (b, n-chunk), one thread per output capsule m.
// Computes Vt -> inner softmax -> agreement (written out) -> qk softmax over m
// (block reduction) -> register-resident nv partial accumulation over the chunk.
__global__ __launch_bounds__(512, 1)
void caps_main(const float* __restrict__ x,     // [B, NIN, 16]
               const float* __restrict__ w,     // [NIN, 4, 4, MM]
               const float* __restrict__ V,     // [MM, 16]
               float* __restrict__ agree_out)   // [B, NIN, MM]
{
    __shared__ float xs[CHUNK][DIN];
    __shared__ float sred[17];

    const int tid   = threadIdx.x;          // m index, 0..511
    const int b     = blockIdx.x / NCHUNK;
    const int chunk = blockIdx.x % NCHUNK;
    const int n0    = chunk * CHUNK;

    // Stage this chunk's input poses into shared (broadcast-reused by all m).
    for (int i = tid; i < CHUNK * DIN; i += 512)
        (&xs[0][0])[i] = x[((size_t)b * NIN + n0) * DIN + i];

    // Initial query V16 for this thread's m (registers).
    float Vq[16];
#pragma unroll
    for (int j = 0; j < 16; j++) Vq[j] = V[(size_t)tid * 16 + j];

    float acc[16];
#pragma unroll
    for (int j = 0; j < 16; j++) acc[j] = 0.f;

    __syncthreads();

    for (int i = 0; i < CHUNK; i++) {
        const int n = n0 + i;
        const float* wn = w + (size_t)n * (4 * 4 * MM) + tid;

        // Vt[a*4+d] = sum_x xs[a*4+x] * w[n, x, d, m]
        float t[16];
#pragma unroll
        for (int xx = 0; xx < 4; xx++) {
#pragma unroll
            for (int d = 0; d < 4; d++) {
                const float wv = wn[(xx * 4 + d) * MM];  // coalesced across m
                if (xx == 0) {
#pragma unroll
                    for (int a = 0; a < 4; a++) t[a * 4 + d] = wv * xs[i][a * 4 + xx];
                } else {
#pragma unroll
                    for (int a = 0; a < 4; a++) t[a * 4 + d] += wv * xs[i][a * 4 + xx];
                }
            }
        }

        // Inner softmax over the 16 (a,d) slots (logits bounded, max-free is safe).
        float s = 0.f;
#pragma unroll
        for (int j = 0; j < 16; j++) { t[j] = __expf(t[j]); s += t[j]; }
        const float inv = 1.0f / s;

        // Agreement with initial query (convex combination of unit-norm row -> |ag|<=1).
        float ag = 0.f;
#pragma unroll
        for (int j = 0; j < 16; j++) ag += t[j] * Vq[j];
        ag *= inv;
        agree_out[((size_t)b * NIN + n) * MM + tid] = ag;

        // qk softmax over m: block-wide sum of exp(ag) (max-free: |ag| <= 1).
        const float e = __expf(ag);
        float v = e;
#pragma unroll
        for (int o = 16; o > 0; o >>= 1) v += __shfl_xor_sync(0xffffffffu, v, o);
        if ((tid & 31) == 0) sred[tid >> 5] = v;
        __syncthreads();
        if (tid < 32) {
            float z = (tid < 16) ? sred[tid] : 0.f;
#pragma unroll
            for (int o = 8; o > 0; o >>= 1) z += __shfl_xor_sync(0xffffffffu, z, o);
            if (tid == 0) sred[16] = z;
        }
        __syncthreads();
        const float qk = e / sred[16];
        __syncthreads();  // protect sred reuse next iteration

        // nv partial: acc += qk * Vs = (qk*inv) * t
        const float qki = qk * inv;
#pragma unroll
        for (int j = 0; j < 16; j++) acc[j] += qki * t[j];
    }

    // Deterministic partial write (no atomics).
    float* p = g_partial + ((((size_t)chunk * BB + b) * MM + tid) << 4);
#pragma unroll
    for (int j = 0; j < 16; j++) p[j] = acc[j];
}

// Reduce chunk partials + LayerNorm over the last 16 dims; writes nv.
__global__ void caps_ln(const float* __restrict__ gamma,
                        const float* __restrict__ beta,
                        float* __restrict__ nv_out)  // [B*MM, 16]
{
    const int r = blockIdx.x * blockDim.x + threadIdx.x;  // row in [0, B*MM)
    if (r >= BB * MM) return;
    const int b = r / MM;
    const int m = r % MM;

    float v[16];
#pragma unroll
    for (int j = 0; j < 16; j++) v[j] = 0.f;
    for (int c = 0; c < NCHUNK; c++) {
        const float* p = g_partial + ((((size_t)c * BB + b) * MM + m) << 4);
#pragma unroll
        for (int j = 0; j < 16; j++) v[j] += p[j];
    }

    float mu = 0.f;
#pragma unroll
    for (int j = 0; j < 16; j++) mu += v[j];
    mu *= (1.0f / 16.0f);
    float var = 0.f;
#pragma unroll
    for (int j = 0; j < 16; j++) { const float d = v[j] - mu; var += d * d; }
    var *= (1.0f / 16.0f);
    const float rs = rsqrtf(var + LN_EPS);

#pragma unroll
    for (int j = 0; j < 16; j++)
        nv_out[(size_t)r * 16 + j] = (v[j] - mu) * rs * gamma[j] + beta[j];
}

extern "C" void kernel_launch(void* const* d_in, const int* in_sizes, int n_in,
                              void* d_out, int out_size)
{
    // metadata order: input, num_iter, w, V, gamma, beta
    const float* x     = (const float*)d_in[0];
    // d_in[1] = num_iter (unused; reference ignores it for num_iter=0)
    const float* w     = (const float*)d_in[2];
    const float* V     = (const float*)d_in[3];
    const float* gamma = (const float*)d_in[4];
    const float* beta  = (const float*)d_in[5];

    float* out      = (float*)d_out;
    float* nv_out   = out;                       // [16,512,16]  = 131072
    float* agree    = out + (size_t)BB * MM * 16; // [16,1024,512] = 8388608

    caps_main<<<BB * NCHUNK, 512>>>(x, w, V, agree);
    caps_ln<<<(BB * MM + 255) / 256, 256>>>(gamma, beta, nv_out);
}

// round 2
// speedup vs baseline: 1.6819x; 1.6819x over previous
#include <cuda_runtime.h>
#include <cstdint>

#define BB     16
#define NIN    1024
#define MM     512
#define NCHUNK 32
#define CHUNK  (NIN / NCHUNK)   // 32
#define BPG    2                // batches per CTA
#define LOG2E  1.4426950408889634f
#define LN_EPS 1e-5f

typedef unsigned long long u64;

// Deterministic per-chunk partial accumulators for nv: [chunk][b][m][16]
__device__ float g_partial[NCHUNK * BB * MM * 16];

__device__ __forceinline__ u64 pack2(float lo, float hi) {
    u64 r; asm("mov.b64 %0,{%1,%2};" : "=l"(r) : "f"(lo), "f"(hi)); return r;
}
__device__ __forceinline__ void unpack2(u64 v, float& lo, float& hi) {
    asm("mov.b64 {%0,%1},%2;" : "=f"(lo), "=f"(hi) : "l"(v));
}
__device__ __forceinline__ u64 fma2(u64 a, u64 b, u64 c) {
    u64 d; asm("fma.rn.f32x2 %0,%1,%2,%3;" : "=l"(d) : "l"(a), "l"(b), "l"(c)); return d;
}
__device__ __forceinline__ u64 add2(u64 a, u64 b) {
    u64 d; asm("add.rn.f32x2 %0,%1,%2;" : "=l"(d) : "l"(a), "l"(b)); return d;
}
__device__ __forceinline__ u64 mul2(u64 a, u64 b) {
    u64 d; asm("mul.rn.f32x2 %0,%1,%2;" : "=l"(d) : "l"(a), "l"(b)); return d;
}
__device__ __forceinline__ float ex2f(float x) {
    float y; asm("ex2.approx.f32 %0,%1;" : "=f"(y) : "f"(x)); return y;
}
__device__ __forceinline__ float rcpf(float x) {
    float y; asm("rcp.approx.f32 %0,%1;" : "=f"(y) : "f"(x)); return y;
}

// Main kernel: CTA = (n-chunk, batch-pair). Thread = output capsule m.
// Packing scheme: slot pairs (8p+d, 8p+4+d) live in one f32x2, p in {0,1}, d in {0..3}.
// t2[p*4+d] = sum_x xsp[p*4+x] * dup(w[x*4+d]) where xsp holds {x[a=2p], x[a=2p+1]}
// pre-scaled by LOG2E so ex2.approx gives exp() directly.
__global__ __launch_bounds__(512, 1)
void caps_main(const float* __restrict__ x,     // [B, NIN, 16]
               const float* __restrict__ w,     // [NIN, 4, 4, MM]
               const float* __restrict__ V,     // [MM, 16]
               float* __restrict__ agree_out)   // [B, NIN, MM]
{
    __shared__ u64  xsp[BPG][CHUNK][8];   // packed, LOG2E-prescaled x
    __shared__ float sred[2][32];         // [buf][bb*16 + wid]

    const int tid   = threadIdx.x;         // m
    const int wid   = tid >> 5;
    const int lane  = tid & 31;
    const int chunk = blockIdx.x % NCHUNK;
    const int bp    = blockIdx.x / NCHUNK; // 0..7
    const int b0    = bp * BPG;
    const int n0    = chunk * CHUNK;

    // Stage + rescale + repack x into shared.
    for (int idx = tid; idx < BPG * CHUNK * 16; idx += 512) {
        const int bb = idx >> 9;
        const int rem = idx & 511;
        const int i = rem >> 4;
        const int j = rem & 15;
        const float v = x[(((size_t)(b0 + bb) * NIN) + n0 + i) * 16 + j] * LOG2E;
        const int a = j >> 2, xc = j & 3, p = a >> 1, h = a & 1;
        ((float*)&xsp[bb][i][p * 4 + xc])[h] = v;
    }

    // Packed initial query for this m (same pairing as t2).
    u64 Vq2[8];
    {
        const float* vm = V + (size_t)tid * 16;
#pragma unroll
        for (int p = 0; p < 2; p++)
#pragma unroll
            for (int d = 0; d < 4; d++)
                Vq2[p * 4 + d] = pack2(vm[8 * p + d], vm[8 * p + 4 + d]);
    }

    u64 acc2[BPG][8];
#pragma unroll
    for (int bb = 0; bb < BPG; bb++)
#pragma unroll
        for (int k = 0; k < 8; k++) acc2[bb][k] = 0ull;

    __syncthreads();

    const float* wbase = w + (size_t)n0 * (16 * MM) + tid;

    for (int i = 0; i < CHUNK; i++) {
        // Load + duplicate the 16 w values for this (n, m). Coalesced across m.
        u64 wd[16];
#pragma unroll
        for (int s = 0; s < 16; s++) {
            const float wv = wbase[(size_t)(i * 16 + s) * MM];
            wd[s] = pack2(wv, wv);
        }

        u64 e2[BPG][8];
        float inv[BPG], eag[BPG];

#pragma unroll
        for (int bb = 0; bb < BPG; bb++) {
            // Pose transform (packed over the 'a' dimension): 32 packed FMA.
            u64 t2[8];
#pragma unroll
            for (int p = 0; p < 2; p++) {
#pragma unroll
                for (int d = 0; d < 4; d++) {
                    u64 acc = mul2(xsp[bb][i][p * 4 + 0], wd[0 * 4 + d]);
                    acc = fma2(xsp[bb][i][p * 4 + 1], wd[1 * 4 + d], acc);
                    acc = fma2(xsp[bb][i][p * 4 + 2], wd[2 * 4 + d], acc);
                    acc = fma2(xsp[bb][i][p * 4 + 3], wd[3 * 4 + d], acc);
                    t2[p * 4 + d] = acc;
                }
            }
            // exp (already log2-scaled): unpack -> ex2 -> repack.
#pragma unroll
            for (int k = 0; k < 8; k++) {
                float lo, hi; unpack2(t2[k], lo, hi);
                e2[bb][k] = pack2(ex2f(lo), ex2f(hi));
            }
            // Inner-softmax denominator (packed tree).
            u64 s01 = add2(add2(e2[bb][0], e2[bb][1]), add2(e2[bb][2], e2[bb][3]));
            u64 s23 = add2(add2(e2[bb][4], e2[bb][5]), add2(e2[bb][6], e2[bb][7]));
            u64 st = add2(s01, s23);
            float slo, shi; unpack2(st, slo, shi);
            inv[bb] = rcpf(slo + shi);
            // Agreement (packed dot with Vq).
            u64 g = mul2(e2[bb][0], Vq2[0]);
#pragma unroll
            for (int k = 1; k < 8; k++) g = fma2(e2[bb][k], Vq2[k], g);
            float glo, ghi; unpack2(g, glo, ghi);
            const float ag = (glo + ghi) * inv[bb];
            agree_out[(((size_t)(b0 + bb) * NIN) + n0 + i) * MM + tid] = ag;
            eag[bb] = ex2f(ag * LOG2E);   // |ag| <= 1, max-free softmax safe
        }

        // Block-wide sum of exp(ag) for both b's, one barrier, double-buffered.
        float v0 = eag[0], v1 = eag[1];
#pragma unroll
        for (int o = 16; o > 0; o >>= 1) {
            v0 += __shfl_xor_sync(0xffffffffu, v0, o);
            v1 += __shfl_xor_sync(0xffffffffu, v1, o);
        }
        const int buf = i & 1;
        if (lane == 0) { sred[buf][wid] = v0; sred[buf][16 + wid] = v1; }
        __syncthreads();
        // Every warp redundantly reduces the 32 partials: lanes 0-15 -> bb0, 16-31 -> bb1.
        float z = sred[buf][lane];
        z += __shfl_xor_sync(0xffffffffu, z, 1);
        z += __shfl_xor_sync(0xffffffffu, z, 2);
        z += __shfl_xor_sync(0xffffffffu, z, 4);
        z += __shfl_xor_sync(0xffffffffu, z, 8);
        const float S0 = __shfl_sync(0xffffffffu, z, 0);
        const float S1 = __shfl_sync(0xffffffffu, z, 16);

        const float q0 = eag[0] * rcpf(S0) * inv[0];
        const float q1 = eag[1] * rcpf(S1) * inv[1];
        const u64 q0d = pack2(q0, q0);
        const u64 q1d = pack2(q1, q1);
#pragma unroll
        for (int k = 0; k < 8; k++) {
            acc2[0][k] = fma2(q0d, e2[0][k], acc2[0][k]);
            acc2[1][k] = fma2(q1d, e2[1][k], acc2[1][k]);
        }
    }

    // Unpack partials to natural slot order and store (float4-friendly).
#pragma unroll
    for (int bb = 0; bb < BPG; bb++) {
        float out[16];
#pragma unroll
        for (int p = 0; p < 2; p++)
#pragma unroll
            for (int d = 0; d < 4; d++) {
                float lo, hi; unpack2(acc2[bb][p * 4 + d], lo, hi);
                out[8 * p + d] = lo;
                out[8 * p + 4 + d] = hi;
            }
        float4* dst = (float4*)(g_partial +
            ((((size_t)chunk * BB + (b0 + bb)) * MM + tid) << 4));
#pragma unroll
        for (int q = 0; q < 4; q++)
            dst[q] = make_float4(out[4 * q], out[4 * q + 1], out[4 * q + 2], out[4 * q + 3]);
    }
}

// Reduce chunk partials + LayerNorm over the last 16 dims; writes nv.
__global__ __launch_bounds__(64)
void caps_ln(const float* __restrict__ gamma,
             const float* __restrict__ beta,
             float* __restrict__ nv_out)  // [B*MM, 16]
{
    const int r = blockIdx.x * blockDim.x + threadIdx.x;  // row in [0, B*MM)
    const int b = r / MM;
    const int m = r % MM;

    float4 v0 = make_float4(0.f, 0.f, 0.f, 0.f);
    float4 v1 = v0, v2 = v0, v3 = v0;
#pragma unroll 4
    for (int c = 0; c < NCHUNK; c++) {
        const float4* p = (const float4*)(g_partial +
            ((((size_t)c * BB + b) * MM + m) << 4));
        const float4 a0 = p[0], a1 = p[1], a2 = p[2], a3 = p[3];
        v0.x += a0.x; v0.y += a0.y; v0.z += a0.z; v0.w += a0.w;
        v1.x += a1.x; v1.y += a1.y; v1.z += a1.z; v1.w += a1.w;
        v2.x += a2.x; v2.y += a2.y; v2.z += a2.z; v2.w += a2.w;
        v3.x += a3.x; v3.y += a3.y; v3.z += a3.z; v3.w += a3.w;
    }

    float v[16] = {v0.x, v0.y, v0.z, v0.w, v1.x, v1.y, v1.z, v1.w,
                   v2.x, v2.y, v2.z, v2.w, v3.x, v3.y, v3.z, v3.w};

    float mu = 0.f;
#pragma unroll
    for (int j = 0; j < 16; j++) mu += v[j];
    mu *= (1.0f / 16.0f);
    float var = 0.f;
#pragma unroll
    for (int j = 0; j < 16; j++) { const float d = v[j] - mu; var += d * d; }
    var *= (1.0f / 16.0f);
    const float rs = rsqrtf(var + LN_EPS);

#pragma unroll
    for (int j = 0; j < 16; j++)
        nv_out[(size_t)r * 16 + j] = (v[j] - mu) * rs * gamma[j] + beta[j];
}

extern "C" void kernel_launch(void* const* d_in, const int* in_sizes, int n_in,
                              void* d_out, int out_size)
{
    // metadata order: input, num_iter, w, V, gamma, beta
    const float* x     = (const float*)d_in[0];
    const float* w     = (const float*)d_in[2];
    const float* V     = (const float*)d_in[3];
    const float* gamma = (const float*)d_in[4];
    const float* beta  = (const float*)d_in[5];

    float* out    = (float*)d_out;
    float* nv_out = out;                          // [16,512,16]   = 131072
    float* agree  = out + (size_t)BB * MM * 16;   // [16,1024,512] = 8388608

    caps_main<<<NCHUNK * (BB / BPG), 512>>>(x, w, V, agree);
    caps_ln<<<(BB * MM) / 64, 64>>>(gamma, beta, nv_out);
}